// round 1
// baseline (speedup 1.0000x reference)
#include <cuda_runtime.h>
#include <math.h>

// ---------------- problem constants ----------------
#define TOTN   131072      // B*N nodes
#define FDIM   64
#define HSD    128
#define RSD    32
#define NPG    4096        // nodes per graph (temporal length)

// ---------------- device scratch (no cudaMalloc allowed) ----------------
__device__ int   g_is64;
__device__ float g_dinv [TOTN];
__device__ float g_A1   [TOTN * FDIM];        // layer1 aggregation / Y
__device__ float g_H1   [TOTN * HSD];         // after GCN1
__device__ float g_H2raw[TOTN * RSD];         // H1 @ W2
__device__ float g_A2   [TOTN * RSD];
__device__ float g_H2   [TOTN * RSD];         // after GCN2
__device__ float g_A3   [TOTN * RSD];         // aggregated input of GCN3
__device__ float g_H3   [TOTN * HSD];         // after GCN3
__device__ float g_C1   [TOTN * HSD];
__device__ float g_C2   [TOTN * RSD];
__device__ float g_C3   [TOTN * HSD];

// ---------------- edge dtype detection ----------------
// edge values < 2^31, so if stored int64 every high word is 0.
__global__ void detect_kernel(const unsigned int* e) {
    if (blockIdx.x == 0 && threadIdx.x == 0) {
        int ok = 1;
        #pragma unroll 1
        for (int i = 0; i < 64; i++)
            if (e[2 * i + 1] != 0u) { ok = 0; break; }
        g_is64 = ok;
    }
}

__device__ __forceinline__ int edge_at(const void* e, int idx, int is64) {
    if (is64) return (int)((const long long*)e)[idx];
    return ((const int*)e)[idx];
}

// ---------------- utility kernels ----------------
__global__ void fill_zero(float* p, int n) {
    int i  = blockIdx.x * blockDim.x + threadIdx.x;
    int st = gridDim.x * blockDim.x;
    for (; i < n; i += st) p[i] = 0.0f;
}

__global__ void degree_kernel(const void* edges, float* deg, int E) {
    int is64 = g_is64;
    int i  = blockIdx.x * blockDim.x + threadIdx.x;
    int st = gridDim.x * blockDim.x;
    for (; i < E; i += st) {
        int d = edge_at(edges, E + i, is64);
        atomicAdd(&deg[d], 1.0f);
    }
}

__global__ void dinv_kernel(float* deg, int n) {
    int i  = blockIdx.x * blockDim.x + threadIdx.x;
    int st = gridDim.x * blockDim.x;
    for (; i < n; i += st) deg[i] = rsqrtf(deg[i] + 1.0f);
}

// ---------------- edge scatter: A[dst] += dinv[src]*dinv[dst]*X[src] ----------------
template <int D>
__global__ void scatter_kernel(const void* edges, const float* __restrict__ dinv,
                               const float* __restrict__ X, float* __restrict__ A, int E) {
    int is64 = g_is64;
    int lane = threadIdx.x & 31;
    int warp = (blockIdx.x * blockDim.x + threadIdx.x) >> 5;
    int nw   = (gridDim.x * blockDim.x) >> 5;
    for (int e = warp; e < E; e += nw) {
        int s = edge_at(edges, e, is64);
        int d = edge_at(edges, E + e, is64);
        float w = dinv[s] * dinv[d];
        if (D == 64) {
            float2 v = ((const float2*)(X + (size_t)s * 64))[lane];
            float* a = A + (size_t)d * 64 + 2 * lane;
            atomicAdd(a,     w * v.x);
            atomicAdd(a + 1, w * v.y);
        } else {
            float v = X[(size_t)s * 32 + lane];
            atomicAdd(A + (size_t)d * 32 + lane, w * v);
        }
    }
}

// ---------------- OUT = dinv*A + dinv^2*X (+bias, relu) ----------------
template <int D, int BIAS_RELU>
__global__ void finish_kernel(const float* __restrict__ A, const float* __restrict__ X,
                              const float* __restrict__ dinv, const float* __restrict__ bias,
                              float* __restrict__ OUT, int n) {
    int i  = blockIdx.x * blockDim.x + threadIdx.x;
    int st = gridDim.x * blockDim.x;
    for (; i < n; i += st) {
        int row = i / D;
        float di = dinv[row];
        float v = di * A[i] + di * di * X[i];
        if (BIAS_RELU) {
            v += bias[i % D];
            v = fmaxf(v, 0.0f);
        }
        OUT[i] = v;
    }
}

// ---------------- tiled fp32 GEMM: C[M,BN] = A[M,K] @ B[K,BN] (+bias)(+relu) ----------------
template <int BM, int BN, int BK, int TM, int TN>
__global__ void __launch_bounds__((BM / TM) * (BN / TN))
gemm_kernel(const float* __restrict__ A, const float* __restrict__ B,
            const float* __restrict__ bias, float* __restrict__ C, int K, int relu) {
    constexpr int TCOLS   = BN / TN;
    constexpr int THREADS = (BM / TM) * (BN / TN);
    __shared__ float As[BK][BM];
    __shared__ float Bs[BK][BN];
    int tid = threadIdx.x;
    int tx = tid % TCOLS, ty = tid / TCOLS;
    size_t row0 = (size_t)blockIdx.x * BM;

    float acc[TM][TN];
    #pragma unroll
    for (int i = 0; i < TM; i++)
        #pragma unroll
        for (int j = 0; j < TN; j++) acc[i][j] = 0.0f;

    for (int k0 = 0; k0 < K; k0 += BK) {
        #pragma unroll
        for (int i = tid; i < BM * BK; i += THREADS) {
            int m = i / BK, kk = i % BK;
            As[kk][m] = A[(row0 + m) * K + k0 + kk];
        }
        #pragma unroll
        for (int i = tid; i < BK * BN; i += THREADS) {
            int kk = i / BN, n = i % BN;
            Bs[kk][n] = B[(size_t)(k0 + kk) * BN + n];
        }
        __syncthreads();
        #pragma unroll
        for (int kk = 0; kk < BK; kk++) {
            float a[TM], b[TN];
            #pragma unroll
            for (int i = 0; i < TM; i++) a[i] = As[kk][ty * TM + i];
            #pragma unroll
            for (int j = 0; j < TN; j++) b[j] = Bs[kk][tx * TN + j];
            #pragma unroll
            for (int i = 0; i < TM; i++)
                #pragma unroll
                for (int j = 0; j < TN; j++)
                    acc[i][j] = fmaf(a[i], b[j], acc[i][j]);
        }
        __syncthreads();
    }
    #pragma unroll
    for (int i = 0; i < TM; i++) {
        size_t r = row0 + ty * TM + i;
        #pragma unroll
        for (int j = 0; j < TN; j++) {
            int n = tx * TN + j;
            float v = acc[i][j];
            if (bias) v += bias[n];
            if (relu) v = fmaxf(v, 0.0f);
            C[r * BN + n] = v;
        }
    }
}

// ---------------- conv1d (k=3, pad=1) over row dim, per-graph boundaries ----------------
// C[r, o] = relu( sum_s sum_i X[r+s-1, i] * W[o, i, s] + bias[o] )
template <int BM, int BN, int BK, int TM, int TN>
__global__ void __launch_bounds__((BM / TM) * (BN / TN))
conv_kernel(const float* __restrict__ X, const float* __restrict__ W,
            const float* __restrict__ bias, float* __restrict__ C, int CIN) {
    constexpr int TCOLS   = BN / TN;
    constexpr int THREADS = (BM / TM) * (BN / TN);
    __shared__ float As[BK][BM + 2];
    __shared__ float Ws[3][BK][BN];
    int tid = threadIdx.x;
    int tx = tid % TCOLS, ty = tid / TCOLS;
    size_t row0 = (size_t)blockIdx.x * BM;
    int zlo = ((row0 % NPG) == 0);          // halo row row0-1 crosses graph boundary
    int zhi = (((row0 + BM) % NPG) == 0);   // halo row row0+BM crosses

    float acc[TM][TN];
    #pragma unroll
    for (int i = 0; i < TM; i++)
        #pragma unroll
        for (int j = 0; j < TN; j++) acc[i][j] = 0.0f;

    for (int k0 = 0; k0 < CIN; k0 += BK) {
        #pragma unroll
        for (int i = tid; i < (BM + 2) * BK; i += THREADS) {
            int r = i / BK, kk = i % BK;
            float v = 0.0f;
            if (!((r == 0 && zlo) || (r == BM + 1 && zhi))) {
                size_t R = row0 - 1 + r;
                v = X[R * CIN + k0 + kk];
            }
            As[kk][r] = v;
        }
        #pragma unroll
        for (int i = tid; i < 3 * BK * BN; i += THREADS) {
            int s = i % 3;
            int t2 = i / 3;
            int n = t2 % BN, kk = t2 / BN;
            Ws[s][kk][n] = W[((size_t)n * CIN + k0 + kk) * 3 + s];
        }
        __syncthreads();
        #pragma unroll
        for (int kk = 0; kk < BK; kk++) {
            float a[TM + 2];
            #pragma unroll
            for (int i = 0; i < TM + 2; i++) a[i] = As[kk][ty * TM + i];
            float b0[TN], b1[TN], b2[TN];
            #pragma unroll
            for (int j = 0; j < TN; j++) {
                b0[j] = Ws[0][kk][tx * TN + j];
                b1[j] = Ws[1][kk][tx * TN + j];
                b2[j] = Ws[2][kk][tx * TN + j];
            }
            #pragma unroll
            for (int i = 0; i < TM; i++)
                #pragma unroll
                for (int j = 0; j < TN; j++) {
                    float v = acc[i][j];
                    v = fmaf(a[i],     b0[j], v);
                    v = fmaf(a[i + 1], b1[j], v);
                    v = fmaf(a[i + 2], b2[j], v);
                    acc[i][j] = v;
                }
        }
        __syncthreads();
    }
    #pragma unroll
    for (int i = 0; i < TM; i++) {
        size_t r = row0 + ty * TM + i;
        #pragma unroll
        for (int j = 0; j < TN; j++) {
            int n = tx * TN + j;
            float v = fmaxf(acc[i][j] + bias[n], 0.0f);
            C[r * BN + n] = v;
        }
    }
}

// ---------------- 3 scalar heads: sigmoid / softplus / sigmoid ----------------
__global__ void heads_kernel(const float* __restrict__ X,
                             const float* __restrict__ Wpi, const float* __restrict__ bpi,
                             const float* __restrict__ Wn,  const float* __restrict__ bn,
                             const float* __restrict__ Wp,  const float* __restrict__ bp,
                             float* __restrict__ out, int M) {
    int lane = threadIdx.x & 31;
    int warp = (blockIdx.x * blockDim.x + threadIdx.x) >> 5;
    int nw   = (gridDim.x * blockDim.x) >> 5;
    float4 wa = ((const float4*)Wpi)[lane];
    float4 wb = ((const float4*)Wn)[lane];
    float4 wc = ((const float4*)Wp)[lane];
    for (int r = warp; r < M; r += nw) {
        float4 x = ((const float4*)(X + (size_t)r * 128))[lane];
        float s1 = x.x * wa.x + x.y * wa.y + x.z * wa.z + x.w * wa.w;
        float s2 = x.x * wb.x + x.y * wb.y + x.z * wb.z + x.w * wb.w;
        float s3 = x.x * wc.x + x.y * wc.y + x.z * wc.z + x.w * wc.w;
        #pragma unroll
        for (int o = 16; o > 0; o >>= 1) {
            s1 += __shfl_xor_sync(0xffffffffu, s1, o);
            s2 += __shfl_xor_sync(0xffffffffu, s2, o);
            s3 += __shfl_xor_sync(0xffffffffu, s3, o);
        }
        if (lane == 0) {
            float zpi = s1 + bpi[0];
            float zn  = s2 + bn[0];
            float zp  = s3 + bp[0];
            out[r]         = 1.0f / (1.0f + expf(-zpi));
            out[M + r]     = (zn > 0.0f) ? (zn + log1pf(expf(-zn))) : log1pf(expf(zn));
            out[2 * M + r] = 1.0f / (1.0f + expf(-zp));
        }
    }
}

// ---------------- launch ----------------
extern "C" void kernel_launch(void* const* d_in, const int* in_sizes, int n_in,
                              void* d_out, int out_size) {
    const float* x     = (const float*)d_in[0];
    const void*  edges = d_in[1];
    // d_in[2] = batch (unused; graphs are contiguous blocks of NPG nodes)
    const float* W1  = (const float*)d_in[3];  const float* b1  = (const float*)d_in[4];
    const float* W2  = (const float*)d_in[5];  const float* b2  = (const float*)d_in[6];
    const float* W3  = (const float*)d_in[7];  const float* b3  = (const float*)d_in[8];
    const float* tW1 = (const float*)d_in[9];  const float* tb1 = (const float*)d_in[10];
    const float* tW2 = (const float*)d_in[11]; const float* tb2 = (const float*)d_in[12];
    const float* tW3 = (const float*)d_in[13]; const float* tb3 = (const float*)d_in[14];
    const float* Wpi = (const float*)d_in[15]; const float* bpi = (const float*)d_in[16];
    const float* Wn  = (const float*)d_in[17]; const float* bn  = (const float*)d_in[18];
    const float* Wp  = (const float*)d_in[19]; const float* bp  = (const float*)d_in[20];
    float* out = (float*)d_out;

    const int TOT = in_sizes[0] / FDIM;   // 131072
    const int E   = in_sizes[1] / 2;      // 1048576

    float *dinv, *A1, *H1, *H2raw, *A2, *H2, *A3, *H3, *C1, *C2, *C3;
    cudaGetSymbolAddress((void**)&dinv,  g_dinv);
    cudaGetSymbolAddress((void**)&A1,    g_A1);
    cudaGetSymbolAddress((void**)&H1,    g_H1);
    cudaGetSymbolAddress((void**)&H2raw, g_H2raw);
    cudaGetSymbolAddress((void**)&A2,    g_A2);
    cudaGetSymbolAddress((void**)&H2,    g_H2);
    cudaGetSymbolAddress((void**)&A3,    g_A3);
    cudaGetSymbolAddress((void**)&H3,    g_H3);
    cudaGetSymbolAddress((void**)&C1,    g_C1);
    cudaGetSymbolAddress((void**)&C2,    g_C2);
    cudaGetSymbolAddress((void**)&C3,    g_C3);

    const int scatterBlocks = (E * 32 + 255) / 256;   // warp per edge

    detect_kernel<<<1, 32>>>((const unsigned int*)edges);

    fill_zero<<<512, 256>>>(dinv, TOT);
    fill_zero<<<4096, 256>>>(A1, TOT * FDIM);
    fill_zero<<<2048, 256>>>(A2, TOT * RSD);
    fill_zero<<<2048, 256>>>(A3, TOT * RSD);

    degree_kernel<<<2048, 256>>>(edges, dinv, E);
    dinv_kernel<<<512, 256>>>(dinv, TOT);

    // ---- GCN layer 1: aggregate raw input (64-dim), then GEMM+bias+relu ----
    scatter_kernel<64><<<scatterBlocks, 256>>>(edges, dinv, x, A1, E);
    finish_kernel<64, 0><<<4096, 256>>>(A1, x, dinv, nullptr, A1, TOT * FDIM);
    gemm_kernel<128, 128, 8, 8, 8><<<TOT / 128, 256>>>(A1, W1, b1, H1, FDIM, 1);

    // ---- GCN layer 2: GEMM to 32, aggregate 32-dim, +bias, relu ----
    gemm_kernel<128, 32, 8, 8, 4><<<TOT / 128, 128>>>(H1, W2, nullptr, H2raw, HSD, 0);
    scatter_kernel<32><<<scatterBlocks, 256>>>(edges, dinv, H2raw, A2, E);
    finish_kernel<32, 1><<<2048, 256>>>(A2, H2raw, dinv, b2, H2, TOT * RSD);

    // ---- GCN layer 3: aggregate 32-dim input, then GEMM+bias+relu ----
    scatter_kernel<32><<<scatterBlocks, 256>>>(edges, dinv, H2, A3, E);
    finish_kernel<32, 0><<<2048, 256>>>(A3, H2, dinv, nullptr, A3, TOT * RSD);
    gemm_kernel<128, 128, 8, 8, 8><<<TOT / 128, 256>>>(A3, W3, b3, H3, RSD, 1);

    // ---- temporal conv stack (k=3, pad=1), relu each ----
    conv_kernel<128, 128, 8, 8, 8><<<TOT / 128, 256>>>(H3, tW1, tb1, C1, HSD);
    conv_kernel<128, 32, 8, 8, 4><<<TOT / 128, 128>>>(C1, tW2, tb2, C2, HSD);
    conv_kernel<128, 128, 8, 8, 8><<<TOT / 128, 256>>>(C2, tW3, tb3, C3, RSD);

    // ---- heads ----
    heads_kernel<<<TOT / 8, 256>>>(C3, Wpi, bpi, Wn, bn, Wp, bp, out, TOT);
}